// round 12
// baseline (speedup 1.0000x reference)
#include <cuda_runtime.h>

#define CROP 14
#define B_ 4
#define N_ 256
#define H_ 256
#define W_ 256
#define C_ 256
#define CQ (C_ / 4)          // float4 quads per pixel = 64

#define NPOS (CROP * CROP)   // 196 positions per box
#define PARTS 7
#define POS_PER_PART 28
// Each CTA handles part `p` of TWO consecutive boxes: 56 positions, 14 groups.
#define POS_PER_CTA (2 * POS_PER_PART)

__device__ __forceinline__ void axis_sample(float lo, float hi, int i,
                                            int& i0, int& i1, float& w, float& v)
{
    // Replicate reference math in float32:
    //   n1 = lo/255 ; n2 = (hi-1)/255 ; t = i/13 ; s = (n1 + (n2-n1)*t) * 255
    const float t  = (float)i / 13.0f;
    const float n1 = lo / 255.0f;
    const float n2 = (hi - 1.0f) / 255.0f;
    const float s  = (n1 + (n2 - n1) * t) * 255.0f;
    v = (s >= 0.0f && s <= 255.0f) ? 1.0f : 0.0f;
    const float f0 = floorf(s);
    w = s - f0;
    i0 = (int)f0;
    i1 = i0 + 1;
    i0 = min(max(i0, 0), H_ - 1);
    i1 = min(max(i1, 0), H_ - 1);
}

__global__ __launch_bounds__(256) void roi_align_kernel(
    const float* __restrict__ boxes,
    const float* __restrict__ fpn,
    float* __restrict__ out)
{
    // Per-position packed corner offsets + weights + output offset.
    __shared__ int4   s_off[POS_PER_CTA];   // (tl, tr, bl, br), float4 units
    __shared__ float4 s_wv [POS_PER_CTA];   // (w00, w01, w10, w11)
    __shared__ int    s_oo [POS_PER_CTA];   // output offset, float4 units

    const int pair = blockIdx.y;       // box-pair index: boxes 2*pair, 2*pair+1
    const int part = blockIdx.x;       // 0..6
    const int b    = pair >> 7;        // batch (= (2*pair)>>8); same for both boxes
    const int base = part * POS_PER_PART;

    const int tid = threadIdx.x;

    // Single-phase setup, ONE barrier: 56 threads, each computes its own
    // position for its own box of the pair.
    if (tid < POS_PER_CTA) {
        const int boxsel = (tid >= POS_PER_PART) ? 1 : 0;
        const int blk    = pair * 2 + boxsel;
        const int pos    = base + tid - boxsel * POS_PER_PART;
        const int py     = pos / CROP;
        const int px     = pos - py * CROP;

        const float4 bx = __ldg(&((const float4*)boxes)[blk]);  // (x1,y1,x2,y2)

        int y0, y1; float wy, vy;
        int x0, x1; float wx, vx;
        axis_sample(bx.y, bx.w, py, y0, y1, wy, vy);
        axis_sample(bx.x, bx.z, px, x0, x1, wx, vx);

        const float v = vy * vx;
        s_off[tid] = make_int4((y0 * W_ + x0) * CQ, (y0 * W_ + x1) * CQ,
                               (y1 * W_ + x0) * CQ, (y1 * W_ + x1) * CQ);
        s_wv[tid]  = make_float4((1.0f - wy) * (1.0f - wx) * v,
                                 (1.0f - wy) * wx * v,
                                 wy * (1.0f - wx) * v,
                                 wy * wx * v);
        s_oo[tid]  = (blk * NPOS + pos) * CQ;
    }
    __syncthreads();

    const float4* img  = (const float4*)(fpn) + (size_t)b * (H_ * W_ * CQ);
    float4*       outp = (float4*)(out);

    const int sub = tid >> 6;   // 4 positions in flight across the CTA
    const int q   = tid & 63;   // float4 index within C

    #pragma unroll 2
    for (int pb = 0; pb < POS_PER_CTA; pb += 4) {
        const int p = pb + sub;
        const int4   o  = s_off[p];
        const float4 w  = s_wv[p];
        const int    oo = s_oo[p];

        const float4 tl = img[o.x + q];
        const float4 tr = img[o.y + q];
        const float4 bl = img[o.z + q];
        const float4 br = img[o.w + q];

        float4 r;
        r.x = tl.x * w.x + tr.x * w.y + bl.x * w.z + br.x * w.w;
        r.y = tl.y * w.x + tr.y * w.y + bl.y * w.z + br.y * w.w;
        r.z = tl.z * w.x + tr.z * w.y + bl.z * w.z + br.z * w.w;
        r.w = tl.w * w.x + tr.w * w.y + bl.w * w.z + br.w * w.w;

        // Streaming store: output is never re-read; keep the image L2-resident.
        __stcs(&outp[oo + q], r);
    }
}

extern "C" void kernel_launch(void* const* d_in, const int* in_sizes, int n_in,
                              void* d_out, int out_size) {
    const float* boxes = (const float*)d_in[0];
    const float* fpn   = (const float*)d_in[1];
    if (n_in >= 2 && in_sizes[0] > in_sizes[1]) {
        boxes = (const float*)d_in[1];
        fpn   = (const float*)d_in[0];
    }
    dim3 grid(PARTS, (B_ * N_) / 2);
    roi_align_kernel<<<grid, 256>>>(boxes, fpn, (float*)d_out);
}

// round 14
// speedup vs baseline: 1.1240x; 1.1240x over previous
#include <cuda_runtime.h>
#include <cstdint>

#define CROP 14
#define B_ 4
#define N_ 256
#define H_ 256
#define W_ 256
#define C_ 256
#define CQ (C_ / 4)          // float4 quads per pixel = 64

// 196 positions per box, split across 7 CTAs of 28 positions each.
#define PARTS 7
#define POS_PER_PART 28

// Image gather with L2 evict_last via cache-hint policy: image lines get L2
// retention priority over the evict-first output stores. Non-volatile so
// ptxas schedules it exactly like a normal load.
__device__ __forceinline__ float4 ldg_el(const float4* p, uint64_t pol)
{
    float4 d;
    asm("ld.global.nc.L2::cache_hint.v4.f32 {%0,%1,%2,%3}, [%4], %5;"
        : "=f"(d.x), "=f"(d.y), "=f"(d.z), "=f"(d.w)
        : "l"(p), "l"(pol));
    return d;
}

__device__ __forceinline__ void axis_sample(float lo, float hi, int i,
                                            int& i0, int& i1, float& w, float& v)
{
    // Replicate reference math in float32:
    //   n1 = lo/255 ; n2 = (hi-1)/255 ; t = i/13 ; s = (n1 + (n2-n1)*t) * 255
    const float t  = (float)i / 13.0f;
    const float n1 = lo / 255.0f;
    const float n2 = (hi - 1.0f) / 255.0f;
    const float s  = (n1 + (n2 - n1) * t) * 255.0f;
    v = (s >= 0.0f && s <= 255.0f) ? 1.0f : 0.0f;
    const float f0 = floorf(s);
    w = s - f0;
    i0 = (int)f0;
    i1 = i0 + 1;
    i0 = min(max(i0, 0), H_ - 1);
    i1 = min(max(i1, 0), H_ - 1);
}

__global__ __launch_bounds__(256) void roi_align_kernel(
    const float* __restrict__ boxes,
    const float* __restrict__ fpn,
    float* __restrict__ out)
{
    // Per-position packed corner offsets (float4 units) + combined weights.
    __shared__ int4   s_off[POS_PER_PART];   // (tl, tr, bl, br)
    __shared__ float4 s_wv [POS_PER_PART];   // (w00, w01, w10, w11)

    const int blk  = blockIdx.y;       // box index: b * N_ + n (box-major)
    const int part = blockIdx.x;       // 0..6
    const int b    = blk >> 8;         // N_ = 256
    const int base = part * POS_PER_PART;

    const int tid = threadIdx.x;

    // Single-phase setup, ONE barrier (round-10 champion structure).
    if (tid < POS_PER_PART) {
        const float4 bx = ((const float4*)boxes)[blk];   // (x1, y1, x2, y2)
        const int pos = base + tid;
        const int py  = pos / CROP;
        const int px  = pos - py * CROP;

        int y0, y1; float wy, vy;
        int x0, x1; float wx, vx;
        axis_sample(bx.y, bx.w, py, y0, y1, wy, vy);
        axis_sample(bx.x, bx.z, px, x0, x1, wx, vx);

        const float v = vy * vx;
        s_off[tid] = make_int4((y0 * W_ + x0) * CQ, (y0 * W_ + x1) * CQ,
                               (y1 * W_ + x0) * CQ, (y1 * W_ + x1) * CQ);
        s_wv[tid]  = make_float4((1.0f - wy) * (1.0f - wx) * v,
                                 (1.0f - wy) * wx * v,
                                 wy * (1.0f - wx) * v,
                                 wy * wx * v);
    }
    __syncthreads();

    // Full-strength evict_last policy for the image gathers.
    uint64_t pol;
    asm("createpolicy.fractional.L2::evict_last.b64 %0, 1.0;" : "=l"(pol));

    const float4* img  = (const float4*)(fpn) + (size_t)b * (H_ * W_ * CQ);
    float4*       outp = (float4*)(out) + ((size_t)blk * (CROP * CROP) + base) * CQ;

    const int sub = tid >> 6;   // 4 positions in flight across the CTA
    const int q   = tid & 63;   // float4 index within C

    #pragma unroll 2
    for (int pb = 0; pb < POS_PER_PART; pb += 4) {
        const int p = pb + sub;
        const int4   o = s_off[p];
        const float4 w = s_wv[p];

        const float4 tl = ldg_el(img + o.x + q, pol);
        const float4 tr = ldg_el(img + o.y + q, pol);
        const float4 bl = ldg_el(img + o.z + q, pol);
        const float4 br = ldg_el(img + o.w + q, pol);

        float4 r;
        r.x = tl.x * w.x + tr.x * w.y + bl.x * w.z + br.x * w.w;
        r.y = tl.y * w.x + tr.y * w.y + bl.y * w.z + br.y * w.w;
        r.z = tl.z * w.x + tr.z * w.y + bl.z * w.z + br.z * w.w;
        r.w = tl.w * w.x + tr.w * w.y + bl.w * w.z + br.w * w.w;

        // Streaming store: output is never re-read; keep the image L2-resident.
        __stcs(&outp[p * CQ + q], r);
    }
}

extern "C" void kernel_launch(void* const* d_in, const int* in_sizes, int n_in,
                              void* d_out, int out_size) {
    const float* boxes = (const float*)d_in[0];
    const float* fpn   = (const float*)d_in[1];
    if (n_in >= 2 && in_sizes[0] > in_sizes[1]) {
        boxes = (const float*)d_in[1];
        fpn   = (const float*)d_in[0];
    }
    dim3 grid(PARTS, B_ * N_);
    roi_align_kernel<<<grid, 256>>>(boxes, fpn, (float*)d_out);
}